// round 1
// baseline (speedup 1.0000x reference)
#include <cuda_runtime.h>
#include <math.h>

// ---------------------------------------------------------------------------
// Problem constants
// ---------------------------------------------------------------------------
#define N_G 50000
#define E_G 800000
#define N_S 10000
#define E_S 160000
#define NF 64
#define NB 8

// ---------------------------------------------------------------------------
// Scratch (device globals; allocation-free)
// ---------------------------------------------------------------------------
__device__ float g_buf0[(size_t)N_G * 256];
__device__ float g_buf1[(size_t)N_G * 256];
__device__ float g_agg [(size_t)N_G * 256];
__device__ float g_pool[2 * NB * 192];
__device__ float g_cnt [2 * NB];
__device__ float g_cat [NB * 448];
__device__ float g_h1  [NB * 600];
__device__ float g_h2  [NB * 256];

// ---------------------------------------------------------------------------
// Edge scatter-add: agg[dst] += x[src]   (float4 loads, scalar atomics)
// ---------------------------------------------------------------------------
__global__ void scatter_add_kernel(const float* __restrict__ x,
                                   const int* __restrict__ src,
                                   const int* __restrict__ dst,
                                   float* __restrict__ agg,
                                   int E, int C, int lgC4)
{
    long long idx = (long long)blockIdx.x * blockDim.x + threadIdx.x;
    int c4cnt = C >> 2;
    if (idx >= (long long)E * c4cnt) return;
    int e = (int)(idx >> lgC4);
    int c = (((int)idx) & (c4cnt - 1)) << 2;
    int s = src[e], d = dst[e];
    const float4 v = *(const float4*)(x + (size_t)s * C + c);
    float* p = agg + (size_t)d * C + c;
    atomicAdd(p + 0, v.x);
    atomicAdd(p + 1, v.y);
    atomicAdd(p + 2, v.z);
    atomicAdd(p + 3, v.w);
}

// ---------------------------------------------------------------------------
// Fused dual GEMM + bias + ELU:
//   out[N][CO] = elu(A1 @ W1^T + A2 @ W2^T + bias)
// A1,A2: [N][C] row-major; W1,W2: [CO][C] row-major; CO % 64 == 0, C % 16 == 0
// Block: 64 rows x 64 cols, 256 threads, 4x4 per thread, BK=16.
// ---------------------------------------------------------------------------
__global__ __launch_bounds__(256)
void gemm_dual_elu(const float* __restrict__ A1, const float* __restrict__ A2,
                   const float* __restrict__ W1, const float* __restrict__ W2,
                   const float* __restrict__ bias, float* __restrict__ out,
                   int N, int C, int CO)
{
    __shared__ float As[16][64];
    __shared__ float Ws[16][64];

    const int tid  = threadIdx.x;
    const int tx   = tid & 15;
    const int ty   = tid >> 4;
    const int row0 = blockIdx.x << 6;
    const int col0 = blockIdx.y << 6;
    const int lr   = tid >> 2;          // 0..63 (loader row)
    const int lk   = (tid & 3) << 2;    // 0,4,8,12 (loader k-offset)

    float acc[4][4];
#pragma unroll
    for (int i = 0; i < 4; i++)
#pragma unroll
        for (int j = 0; j < 4; j++) acc[i][j] = 0.f;

    const int r    = row0 + lr;
    const int wrow = col0 + lr;   // < CO always (CO multiple of 64)
    const int Ktot = 2 * C;

    for (int kt = 0; kt < Ktot; kt += 16) {
        const float* A; const float* W; int kb;
        if (kt < C) { A = A1; W = W1; kb = kt; }
        else        { A = A2; W = W2; kb = kt - C; }

        float4 av = make_float4(0.f, 0.f, 0.f, 0.f);
        if (r < N) av = *(const float4*)(A + (size_t)r * C + kb + lk);
        float4 wv = *(const float4*)(W + (size_t)wrow * C + kb + lk);

        __syncthreads();
        As[lk + 0][lr] = av.x; As[lk + 1][lr] = av.y;
        As[lk + 2][lr] = av.z; As[lk + 3][lr] = av.w;
        Ws[lk + 0][lr] = wv.x; Ws[lk + 1][lr] = wv.y;
        Ws[lk + 2][lr] = wv.z; Ws[lk + 3][lr] = wv.w;
        __syncthreads();

#pragma unroll
        for (int k = 0; k < 16; k++) {
            float4 a = *(const float4*)&As[k][ty << 2];
            float4 w = *(const float4*)&Ws[k][tx << 2];
            float af[4] = {a.x, a.y, a.z, a.w};
            float wf[4] = {w.x, w.y, w.z, w.w};
#pragma unroll
            for (int i = 0; i < 4; i++)
#pragma unroll
                for (int j = 0; j < 4; j++) acc[i][j] += af[i] * wf[j];
        }
    }

#pragma unroll
    for (int i = 0; i < 4; i++) {
        int rr = row0 + (ty << 2) + i;
        if (rr >= N) break;
#pragma unroll
        for (int j = 0; j < 4; j++) {
            int cc = col0 + (tx << 2) + j;
            float v = acc[i][j] + bias[cc];
            v = v > 0.f ? v : expm1f(v);
            out[(size_t)rr * CO + cc] = v;
        }
    }
}

// ---------------------------------------------------------------------------
// Mean-pool (C fixed at 192), smem-staged to limit global atomic contention
// ---------------------------------------------------------------------------
__global__ __launch_bounds__(256)
void pool_sum_kernel(const float* __restrict__ x, const int* __restrict__ batch,
                     float* __restrict__ sums, int N)
{
    __shared__ float acc[NB * 192];
    for (int i = threadIdx.x; i < NB * 192; i += 256) acc[i] = 0.f;
    __syncthreads();

    int n0  = blockIdx.x * 256;
    int cnt = N - n0; if (cnt > 256) cnt = 256;
    int total = cnt * 192;
    for (int idx = threadIdx.x; idx < total; idx += 256) {
        int nl = idx / 192;
        int c  = idx - nl * 192;
        int n  = n0 + nl;
        atomicAdd(&acc[batch[n] * 192 + c], x[(size_t)n * 192 + c]);
    }
    __syncthreads();
    for (int i = threadIdx.x; i < NB * 192; i += 256) {
        float v = acc[i];
        if (v != 0.f) atomicAdd(&sums[i], v);
    }
}

__global__ void count_kernel(const int* __restrict__ batch, float* __restrict__ cnt, int N)
{
    __shared__ float c[NB];
    if (threadIdx.x < NB) c[threadIdx.x] = 0.f;
    __syncthreads();
    int n = blockIdx.x * blockDim.x + threadIdx.x;
    if (n < N) atomicAdd(&c[batch[n]], 1.f);
    __syncthreads();
    if (threadIdx.x < NB) {
        float v = c[threadIdx.x];
        if (v != 0.f) atomicAdd(&cnt[threadIdx.x], v);
    }
}

// ---------------------------------------------------------------------------
// Finalize pooled means + concat with point -> cat[8][448]
// ---------------------------------------------------------------------------
__global__ void cat_kernel(const float* __restrict__ sums1, const float* __restrict__ cnt1,
                           const float* __restrict__ sums2, const float* __restrict__ cnt2,
                           const float* __restrict__ point, float* __restrict__ cat)
{
    int i = blockIdx.x * blockDim.x + threadIdx.x;
    if (i >= NB * 448) return;
    int b = i / 448, c = i - b * 448;
    float v;
    if (c < 192)      v = sums1[b * 192 + c]         / fmaxf(cnt1[b], 1.f);
    else if (c < 384) v = sums2[b * 192 + (c - 192)] / fmaxf(cnt2[b], 1.f);
    else              v = point[b * NF + (c - 384)];
    cat[i] = v;
}

// ---------------------------------------------------------------------------
// FC layer: one warp per output element. act: 0 = none, 1 = relu
// ---------------------------------------------------------------------------
__global__ void fc_kernel(const float* __restrict__ in, const float* __restrict__ W,
                          const float* __restrict__ bias, float* __restrict__ out,
                          int Bn, int K, int O, int act)
{
    int warp = (blockIdx.x * blockDim.x + threadIdx.x) >> 5;
    int lane = threadIdx.x & 31;
    if (warp >= Bn * O) return;
    int b = warp / O, o = warp - b * O;
    const float* ip = in + (size_t)b * K;
    const float* wp = W  + (size_t)o * K;
    float s = 0.f;
    for (int k = lane; k < K; k += 32) s += ip[k] * wp[k];
#pragma unroll
    for (int off = 16; off; off >>= 1) s += __shfl_xor_sync(0xFFFFFFFFu, s, off);
    if (lane == 0) {
        s += bias[o];
        if (act) s = fmaxf(s, 0.f);
        out[(size_t)b * O + o] = s;
    }
}

// ---------------------------------------------------------------------------
// Host-side branch driver
// ---------------------------------------------------------------------------
static void run_branch(const float* x_in, const int* ei, const int* batch,
                       int N, int E,
                       const float* W1r, const float* W1n, const float* B1,
                       const float* W2r, const float* W2n, const float* B2,
                       const float* W3r, const float* W3n, const float* B3,
                       float* buf0, float* buf1, float* agg,
                       float* sums, float* cnt)
{
    const int* src = ei;
    const int* dst = ei + E;

    // L1: C=64 -> CO=128
    cudaMemsetAsync(agg, 0, (size_t)N * 64 * sizeof(float));
    {
        long long tot = (long long)E * (64 / 4);
        scatter_add_kernel<<<(unsigned)((tot + 255) / 256), 256>>>(x_in, src, dst, agg, E, 64, 4);
        gemm_dual_elu<<<dim3((N + 63) / 64, 128 / 64), 256>>>(agg, x_in, W1r, W1n, B1, buf0, N, 64, 128);
    }
    // L2: C=128 -> CO=256
    cudaMemsetAsync(agg, 0, (size_t)N * 128 * sizeof(float));
    {
        long long tot = (long long)E * (128 / 4);
        scatter_add_kernel<<<(unsigned)((tot + 255) / 256), 256>>>(buf0, src, dst, agg, E, 128, 5);
        gemm_dual_elu<<<dim3((N + 63) / 64, 256 / 64), 256>>>(agg, buf0, W2r, W2n, B2, buf1, N, 128, 256);
    }
    // L3: C=256 -> CO=192
    cudaMemsetAsync(agg, 0, (size_t)N * 256 * sizeof(float));
    {
        long long tot = (long long)E * (256 / 4);
        scatter_add_kernel<<<(unsigned)((tot + 255) / 256), 256>>>(buf1, src, dst, agg, E, 256, 6);
        gemm_dual_elu<<<dim3((N + 63) / 64, 192 / 64), 256>>>(agg, buf1, W3r, W3n, B3, buf0, N, 256, 192);
    }
    // mean-pool
    pool_sum_kernel<<<(N + 255) / 256, 256>>>(buf0, batch, sums, N);
    count_kernel  <<<(N + 255) / 256, 256>>>(batch, cnt, N);
}

// ---------------------------------------------------------------------------
// kernel_launch
// ---------------------------------------------------------------------------
extern "C" void kernel_launch(void* const* d_in, const int* in_sizes, int n_in,
                              void* d_out, int out_size)
{
    // Resolve input ordering: signature order (weights at idx 3) vs dict order
    // (edge_index at idx 3, size 2*E_G = 1,600,000).
    int IDX[31];
    bool dict_order = (in_sizes[3] == 2 * E_G);
    if (dict_order) {
        // 0 gx,1 sx,2 pt,3 gei,4 gb,5 sei,6 sb,7..15 gW,16..24 sW,25..30 mlp
        int m[31] = {0,1,2, 7,8,9,10,11,12,13,14,15, 16,17,18,19,20,21,22,23,24,
                     25,26,27,28,29,30, 3,4,5,6};
        for (int i = 0; i < 31; i++) IDX[i] = m[i];
    } else {
        // signature order
        for (int i = 0; i < 31; i++) IDX[i] = i;
    }
    // Canonical indices (signature layout):
    const float* graph_x    = (const float*)d_in[IDX[0]];
    const float* subgraph_x = (const float*)d_in[IDX[1]];
    const float* point      = (const float*)d_in[IDX[2]];
    const float* gW[9]; const float* sW[9];
    for (int i = 0; i < 9; i++) gW[i] = (const float*)d_in[IDX[3 + i]];
    for (int i = 0; i < 9; i++) sW[i] = (const float*)d_in[IDX[12 + i]];
    const float* l1W = (const float*)d_in[IDX[21]];
    const float* l1b = (const float*)d_in[IDX[22]];
    const float* l2W = (const float*)d_in[IDX[23]];
    const float* l2b = (const float*)d_in[IDX[24]];
    const float* l3W = (const float*)d_in[IDX[25]];
    const float* l3b = (const float*)d_in[IDX[26]];
    const int* g_ei   = (const int*)d_in[IDX[27]];
    const int* g_bat  = (const int*)d_in[IDX[28]];
    const int* s_ei   = (const int*)d_in[IDX[29]];
    const int* s_bat  = (const int*)d_in[IDX[30]];

    float *buf0, *buf1, *agg, *pool, *cnt, *cat, *h1, *h2;
    cudaGetSymbolAddress((void**)&buf0, g_buf0);
    cudaGetSymbolAddress((void**)&buf1, g_buf1);
    cudaGetSymbolAddress((void**)&agg,  g_agg);
    cudaGetSymbolAddress((void**)&pool, g_pool);
    cudaGetSymbolAddress((void**)&cnt,  g_cnt);
    cudaGetSymbolAddress((void**)&cat,  g_cat);
    cudaGetSymbolAddress((void**)&h1,   g_h1);
    cudaGetSymbolAddress((void**)&h2,   g_h2);

    float* out = (float*)d_out;

    cudaMemsetAsync(pool, 0, 2 * NB * 192 * sizeof(float));
    cudaMemsetAsync(cnt,  0, 2 * NB * sizeof(float));

    // Graph branch
    run_branch(graph_x, g_ei, g_bat, N_G, E_G,
               gW[0], gW[1], gW[2], gW[3], gW[4], gW[5], gW[6], gW[7], gW[8],
               buf0, buf1, agg, pool, cnt);
    // Subgraph branch (reuses scratch)
    run_branch(subgraph_x, s_ei, s_bat, N_S, E_S,
               sW[0], sW[1], sW[2], sW[3], sW[4], sW[5], sW[6], sW[7], sW[8],
               buf0, buf1, agg, pool + NB * 192, cnt + NB);

    // Concat + MLP
    cat_kernel<<<(NB * 448 + 255) / 256, 256>>>(pool, cnt, pool + NB * 192, cnt + NB, point, cat);
    {
        int warps = NB * 600;
        fc_kernel<<<(warps * 32 + 255) / 256, 256>>>(cat, l1W, l1b, h1, NB, 448, 600, 1);
    }
    {
        int warps = NB * 256;
        fc_kernel<<<(warps * 32 + 255) / 256, 256>>>(h1, l2W, l2b, h2, NB, 600, 256, 1);
    }
    {
        int warps = NB * 64;
        fc_kernel<<<(warps * 32 + 255) / 256, 256>>>(h2, l3W, l3b, out, NB, 256, 64, 0);
    }
    (void)n_in; (void)out_size;
}

// round 2
// speedup vs baseline: 1.6320x; 1.6320x over previous
#include <cuda_runtime.h>
#include <math.h>

// ---------------------------------------------------------------------------
// Problem constants
// ---------------------------------------------------------------------------
#define N_G 50000
#define E_G 800000
#define N_S 10000
#define E_S 160000
#define NF 64
#define NB 8

// ---------------------------------------------------------------------------
// Scratch (device globals; allocation-free)
// ---------------------------------------------------------------------------
__device__ float g_buf0[(size_t)N_G * 256];
__device__ float g_buf1[(size_t)N_G * 256];
__device__ float g_agg [(size_t)N_G * 256];
__device__ float g_pool[2 * NB * 192];
__device__ float g_cnt [2 * NB];
__device__ float g_cat [NB * 448];
__device__ float g_h1  [NB * 600];
__device__ float g_h2  [NB * 256];
// CSR scratch (max = graph branch, reused by subgraph branch)
__device__ int   g_rowptr[N_G + 1];
__device__ int   g_cursor[N_G];
__device__ int   g_srcs  [E_G];
__device__ int   g_bsums [512];

// ---------------------------------------------------------------------------
// CSR build: histogram -> 2-level exclusive scan -> cursor fill
// ---------------------------------------------------------------------------
__global__ void hist_kernel(const int* __restrict__ dst, int* __restrict__ counts, int E)
{
    int e = blockIdx.x * blockDim.x + threadIdx.x;
    if (e < E) atomicAdd(&counts[dst[e]], 1);
}

// per-block sums of 256-element chunks
__global__ void scan1_kernel(const int* __restrict__ counts, int* __restrict__ bsums, int N)
{
    __shared__ int s[256];
    int i = blockIdx.x * 256 + threadIdx.x;
    int v = (i < N) ? counts[i] : 0;
    s[threadIdx.x] = v;
    __syncthreads();
    for (int off = 128; off > 0; off >>= 1) {
        if (threadIdx.x < off) s[threadIdx.x] += s[threadIdx.x + off];
        __syncthreads();
    }
    if (threadIdx.x == 0) bsums[blockIdx.x] = s[0];
}

// single-block exclusive scan of block sums (nb <= 256); also writes rowptr[N]=E
__global__ void scan2_kernel(int* __restrict__ bsums, int nb, int* __restrict__ rowptr,
                             int N, int E)
{
    __shared__ int s[256];
    int tid = threadIdx.x;
    int v = (tid < nb) ? bsums[tid] : 0;
    s[tid] = v;
    __syncthreads();
    for (int off = 1; off < 256; off <<= 1) {
        int t = (tid >= off) ? s[tid - off] : 0;
        __syncthreads();
        s[tid] += t;
        __syncthreads();
    }
    if (tid < nb) bsums[tid] = s[tid] - v;   // exclusive
    if (tid == 0) rowptr[N] = E;
}

// per-block exclusive scan + offset; in-place counts -> rowptr; also init cursor
__global__ void scan3_kernel(int* __restrict__ rowptr, const int* __restrict__ bsums,
                             int* __restrict__ cursor, int N)
{
    __shared__ int s[256];
    int tid = threadIdx.x;
    int i = blockIdx.x * 256 + tid;
    int v = (i < N) ? rowptr[i] : 0;
    s[tid] = v;
    __syncthreads();
    for (int off = 1; off < 256; off <<= 1) {
        int t = (tid >= off) ? s[tid - off] : 0;
        __syncthreads();
        s[tid] += t;
        __syncthreads();
    }
    if (i < N) {
        int val = s[tid] - v + bsums[blockIdx.x];
        rowptr[i] = val;
        cursor[i] = val;
    }
}

__global__ void fill_kernel(const int* __restrict__ src, const int* __restrict__ dst,
                            int* __restrict__ cursor, int* __restrict__ srcs, int E)
{
    int e = blockIdx.x * blockDim.x + threadIdx.x;
    if (e >= E) return;
    int d = dst[e];
    int p = atomicAdd(&cursor[d], 1);
    srcs[p] = src[e];
}

// ---------------------------------------------------------------------------
// CSR gather aggregation: agg[n][c] = sum_{e in in(n)} x[srcs[e]][c]
// C in {64,128,256}; block = 256 threads covers (256>>lgC) nodes
// ---------------------------------------------------------------------------
__global__ __launch_bounds__(256)
void gather_kernel(const float* __restrict__ x, const int* __restrict__ rowptr,
                   const int* __restrict__ srcs, float* __restrict__ agg,
                   int N, int C, int lgC)
{
    int c    = threadIdx.x & (C - 1);
    int node = blockIdx.x * (256 >> lgC) + (threadIdx.x >> lgC);
    if (node >= N) return;
    int b = rowptr[node];
    int e = rowptr[node + 1];
    float acc0 = 0.f, acc1 = 0.f;
    int i = b;
    for (; i + 2 <= e; i += 2) {
        int s0 = srcs[i], s1 = srcs[i + 1];
        acc0 += x[(size_t)s0 * C + c];
        acc1 += x[(size_t)s1 * C + c];
    }
    if (i < e) acc0 += x[(size_t)srcs[i] * C + c];
    agg[(size_t)node * C + c] = acc0 + acc1;
}

// ---------------------------------------------------------------------------
// Fused dual GEMM + bias + ELU:
//   out[N][CO] = elu(A1 @ W1^T + A2 @ W2^T + bias)
// Block tile 128x64, BK=16, 256 threads, 8x4 per thread, double-buffered smem.
// CO % 64 == 0, C % 16 == 0.
// ---------------------------------------------------------------------------
#define BM 128
#define BN 64
#define BK 16

__global__ __launch_bounds__(256)
void gemm_dual_elu(const float* __restrict__ A1, const float* __restrict__ A2,
                   const float* __restrict__ W1, const float* __restrict__ W2,
                   const float* __restrict__ bias, float* __restrict__ out,
                   int N, int C, int CO)
{
    __shared__ float As[2][BK][BM];
    __shared__ float Bs[2][BK][BN];

    const int tid  = threadIdx.x;
    const int row0 = blockIdx.x * BM;
    const int col0 = blockIdx.y * BN;

    // loader mapping
    const int ar = tid >> 1;            // 0..127
    const int ak = (tid & 1) << 3;      // 0 or 8
    const int br = tid >> 2;            // 0..63
    const int bk = (tid & 3) << 2;      // 0,4,8,12

    // compute mapping
    const int tm = tid >> 4;            // 0..15 -> rows tm*8..+7
    const int tn = tid & 15;            // 0..15 -> cols tn*4..+3

    const int ga_row = row0 + ar;
    const int gb_row = col0 + br;       // always < CO

    float acc[8][4];
#pragma unroll
    for (int i = 0; i < 8; i++)
#pragma unroll
        for (int j = 0; j < 4; j++) acc[i][j] = 0.f;

    const int Ktot = 2 * C;
    const int nk   = Ktot / BK;

    float4 a0, a1, b0;

    // --- load tile 0 into regs ---
    {
        const float* A = A1; const float* W = W1; int kb = 0;
        a0 = make_float4(0.f, 0.f, 0.f, 0.f); a1 = a0;
        if (ga_row < N) {
            a0 = *(const float4*)(A + (size_t)ga_row * C + kb + ak);
            a1 = *(const float4*)(A + (size_t)ga_row * C + kb + ak + 4);
        }
        b0 = *(const float4*)(W + (size_t)gb_row * C + kb + bk);
    }
    int buf = 0;
    // store tile 0
    As[buf][ak + 0][ar] = a0.x; As[buf][ak + 1][ar] = a0.y;
    As[buf][ak + 2][ar] = a0.z; As[buf][ak + 3][ar] = a0.w;
    As[buf][ak + 4][ar] = a1.x; As[buf][ak + 5][ar] = a1.y;
    As[buf][ak + 6][ar] = a1.z; As[buf][ak + 7][ar] = a1.w;
    Bs[buf][bk + 0][br] = b0.x; Bs[buf][bk + 1][br] = b0.y;
    Bs[buf][bk + 2][br] = b0.z; Bs[buf][bk + 3][br] = b0.w;
    __syncthreads();

    for (int t = 0; t < nk; t++) {
        // prefetch next tile to regs
        if (t + 1 < nk) {
            int kt = (t + 1) * BK;
            const float* A; const float* W; int kb;
            if (kt < C) { A = A1; W = W1; kb = kt; }
            else        { A = A2; W = W2; kb = kt - C; }
            a0 = make_float4(0.f, 0.f, 0.f, 0.f); a1 = a0;
            if (ga_row < N) {
                a0 = *(const float4*)(A + (size_t)ga_row * C + kb + ak);
                a1 = *(const float4*)(A + (size_t)ga_row * C + kb + ak + 4);
            }
            b0 = *(const float4*)(W + (size_t)gb_row * C + kb + bk);
        }

        // compute on current buffer
#pragma unroll
        for (int k = 0; k < BK; k++) {
            float a_frag[8], b_frag[4];
            *(float4*)&a_frag[0] = *(const float4*)&As[buf][k][tm * 8];
            *(float4*)&a_frag[4] = *(const float4*)&As[buf][k][tm * 8 + 4];
            *(float4*)&b_frag[0] = *(const float4*)&Bs[buf][k][tn * 4];
#pragma unroll
            for (int i = 0; i < 8; i++)
#pragma unroll
                for (int j = 0; j < 4; j++)
                    acc[i][j] += a_frag[i] * b_frag[j];
        }

        if (t + 1 < nk) {
            int nb = buf ^ 1;
            As[nb][ak + 0][ar] = a0.x; As[nb][ak + 1][ar] = a0.y;
            As[nb][ak + 2][ar] = a0.z; As[nb][ak + 3][ar] = a0.w;
            As[nb][ak + 4][ar] = a1.x; As[nb][ak + 5][ar] = a1.y;
            As[nb][ak + 6][ar] = a1.z; As[nb][ak + 7][ar] = a1.w;
            Bs[nb][bk + 0][br] = b0.x; Bs[nb][bk + 1][br] = b0.y;
            Bs[nb][bk + 2][br] = b0.z; Bs[nb][bk + 3][br] = b0.w;
            __syncthreads();
            buf = nb;
        }
    }

    // epilogue: bias + ELU
    float4 bv = *(const float4*)(bias + col0 + tn * 4);
    float bf[4] = {bv.x, bv.y, bv.z, bv.w};
#pragma unroll
    for (int i = 0; i < 8; i++) {
        int rr = row0 + tm * 8 + i;
        if (rr >= N) break;
#pragma unroll
        for (int j = 0; j < 4; j++) {
            int cc = col0 + tn * 4 + j;
            float v = acc[i][j] + bf[j];
            v = v > 0.f ? v : expm1f(v);
            out[(size_t)rr * CO + cc] = v;
        }
    }
}

// ---------------------------------------------------------------------------
// Mean-pool (C fixed at 192), smem-staged
// ---------------------------------------------------------------------------
__global__ __launch_bounds__(256)
void pool_sum_kernel(const float* __restrict__ x, const int* __restrict__ batch,
                     float* __restrict__ sums, int N)
{
    __shared__ float acc[NB * 192];
    for (int i = threadIdx.x; i < NB * 192; i += 256) acc[i] = 0.f;
    __syncthreads();

    int n0  = blockIdx.x * 256;
    int cnt = N - n0; if (cnt > 256) cnt = 256;
    int total = cnt * 192;
    for (int idx = threadIdx.x; idx < total; idx += 256) {
        int nl = idx / 192;
        int c  = idx - nl * 192;
        int n  = n0 + nl;
        atomicAdd(&acc[batch[n] * 192 + c], x[(size_t)n * 192 + c]);
    }
    __syncthreads();
    for (int i = threadIdx.x; i < NB * 192; i += 256) {
        float v = acc[i];
        if (v != 0.f) atomicAdd(&sums[i], v);
    }
}

__global__ void count_kernel(const int* __restrict__ batch, float* __restrict__ cnt, int N)
{
    __shared__ float c[NB];
    if (threadIdx.x < NB) c[threadIdx.x] = 0.f;
    __syncthreads();
    int n = blockIdx.x * blockDim.x + threadIdx.x;
    if (n < N) atomicAdd(&c[batch[n]], 1.f);
    __syncthreads();
    if (threadIdx.x < NB) {
        float v = c[threadIdx.x];
        if (v != 0.f) atomicAdd(&cnt[threadIdx.x], v);
    }
}

// ---------------------------------------------------------------------------
// Finalize pooled means + concat with point -> cat[8][448]
// ---------------------------------------------------------------------------
__global__ void cat_kernel(const float* __restrict__ sums1, const float* __restrict__ cnt1,
                           const float* __restrict__ sums2, const float* __restrict__ cnt2,
                           const float* __restrict__ point, float* __restrict__ cat)
{
    int i = blockIdx.x * blockDim.x + threadIdx.x;
    if (i >= NB * 448) return;
    int b = i / 448, c = i - b * 448;
    float v;
    if (c < 192)      v = sums1[b * 192 + c]         / fmaxf(cnt1[b], 1.f);
    else if (c < 384) v = sums2[b * 192 + (c - 192)] / fmaxf(cnt2[b], 1.f);
    else              v = point[b * NF + (c - 384)];
    cat[i] = v;
}

// ---------------------------------------------------------------------------
// FC layer: one warp per output element. act: 0 = none, 1 = relu
// ---------------------------------------------------------------------------
__global__ void fc_kernel(const float* __restrict__ in, const float* __restrict__ W,
                          const float* __restrict__ bias, float* __restrict__ out,
                          int Bn, int K, int O, int act)
{
    int warp = (blockIdx.x * blockDim.x + threadIdx.x) >> 5;
    int lane = threadIdx.x & 31;
    if (warp >= Bn * O) return;
    int b = warp / O, o = warp - b * O;
    const float* ip = in + (size_t)b * K;
    const float* wp = W  + (size_t)o * K;
    float s = 0.f;
    for (int k = lane; k < K; k += 32) s += ip[k] * wp[k];
#pragma unroll
    for (int off = 16; off; off >>= 1) s += __shfl_xor_sync(0xFFFFFFFFu, s, off);
    if (lane == 0) {
        s += bias[o];
        if (act) s = fmaxf(s, 0.f);
        out[(size_t)b * O + o] = s;
    }
}

// ---------------------------------------------------------------------------
// Host-side branch driver
// ---------------------------------------------------------------------------
static void run_branch(const float* x_in, const int* ei, const int* batch,
                       int N, int E,
                       const float* W1r, const float* W1n, const float* B1,
                       const float* W2r, const float* W2n, const float* B2,
                       const float* W3r, const float* W3n, const float* B3,
                       float* buf0, float* buf1, float* agg,
                       int* rowptr, int* cursor, int* srcs, int* bsums,
                       float* sums, float* cnt)
{
    const int* src = ei;
    const int* dst = ei + E;

    // ---- build CSR by dst (edges constant across the 3 layers) ----
    cudaMemsetAsync(rowptr, 0, (size_t)(N + 1) * sizeof(int));
    hist_kernel<<<(E + 255) / 256, 256>>>(dst, rowptr, E);
    int nb = (N + 255) / 256;
    scan1_kernel<<<nb, 256>>>(rowptr, bsums, N);
    scan2_kernel<<<1, 256>>>(bsums, nb, rowptr, N, E);
    scan3_kernel<<<nb, 256>>>(rowptr, bsums, cursor, N);
    fill_kernel<<<(E + 255) / 256, 256>>>(src, dst, cursor, srcs, E);

    // L1: C=64 -> CO=128
    gather_kernel<<<(N + 3) / 4, 256>>>(x_in, rowptr, srcs, agg, N, 64, 6);
    gemm_dual_elu<<<dim3((N + BM - 1) / BM, 128 / BN), 256>>>(agg, x_in, W1r, W1n, B1, buf0, N, 64, 128);
    // L2: C=128 -> CO=256
    gather_kernel<<<(N + 1) / 2, 256>>>(buf0, rowptr, srcs, agg, N, 128, 7);
    gemm_dual_elu<<<dim3((N + BM - 1) / BM, 256 / BN), 256>>>(agg, buf0, W2r, W2n, B2, buf1, N, 128, 256);
    // L3: C=256 -> CO=192
    gather_kernel<<<N, 256>>>(buf1, rowptr, srcs, agg, N, 256, 8);
    gemm_dual_elu<<<dim3((N + BM - 1) / BM, 192 / BN), 256>>>(agg, buf1, W3r, W3n, B3, buf0, N, 256, 192);

    // mean-pool
    pool_sum_kernel<<<(N + 255) / 256, 256>>>(buf0, batch, sums, N);
    count_kernel  <<<(N + 255) / 256, 256>>>(batch, cnt, N);
}

// ---------------------------------------------------------------------------
// kernel_launch
// ---------------------------------------------------------------------------
extern "C" void kernel_launch(void* const* d_in, const int* in_sizes, int n_in,
                              void* d_out, int out_size)
{
    // Resolve input ordering: signature order vs dict order
    int IDX[31];
    bool dict_order = (in_sizes[3] == 2 * E_G);
    if (dict_order) {
        int m[31] = {0,1,2, 7,8,9,10,11,12,13,14,15, 16,17,18,19,20,21,22,23,24,
                     25,26,27,28,29,30, 3,4,5,6};
        for (int i = 0; i < 31; i++) IDX[i] = m[i];
    } else {
        for (int i = 0; i < 31; i++) IDX[i] = i;
    }
    const float* graph_x    = (const float*)d_in[IDX[0]];
    const float* subgraph_x = (const float*)d_in[IDX[1]];
    const float* point      = (const float*)d_in[IDX[2]];
    const float* gW[9]; const float* sW[9];
    for (int i = 0; i < 9; i++) gW[i] = (const float*)d_in[IDX[3 + i]];
    for (int i = 0; i < 9; i++) sW[i] = (const float*)d_in[IDX[12 + i]];
    const float* l1W = (const float*)d_in[IDX[21]];
    const float* l1b = (const float*)d_in[IDX[22]];
    const float* l2W = (const float*)d_in[IDX[23]];
    const float* l2b = (const float*)d_in[IDX[24]];
    const float* l3W = (const float*)d_in[IDX[25]];
    const float* l3b = (const float*)d_in[IDX[26]];
    const int* g_ei   = (const int*)d_in[IDX[27]];
    const int* g_bat  = (const int*)d_in[IDX[28]];
    const int* s_ei   = (const int*)d_in[IDX[29]];
    const int* s_bat  = (const int*)d_in[IDX[30]];

    float *buf0, *buf1, *agg, *pool, *cnt, *cat, *h1, *h2;
    int *rowptr, *cursor, *srcs, *bsums;
    cudaGetSymbolAddress((void**)&buf0, g_buf0);
    cudaGetSymbolAddress((void**)&buf1, g_buf1);
    cudaGetSymbolAddress((void**)&agg,  g_agg);
    cudaGetSymbolAddress((void**)&pool, g_pool);
    cudaGetSymbolAddress((void**)&cnt,  g_cnt);
    cudaGetSymbolAddress((void**)&cat,  g_cat);
    cudaGetSymbolAddress((void**)&h1,   g_h1);
    cudaGetSymbolAddress((void**)&h2,   g_h2);
    cudaGetSymbolAddress((void**)&rowptr, g_rowptr);
    cudaGetSymbolAddress((void**)&cursor, g_cursor);
    cudaGetSymbolAddress((void**)&srcs,   g_srcs);
    cudaGetSymbolAddress((void**)&bsums,  g_bsums);

    float* out = (float*)d_out;

    cudaMemsetAsync(pool, 0, 2 * NB * 192 * sizeof(float));
    cudaMemsetAsync(cnt,  0, 2 * NB * sizeof(float));

    // Graph branch
    run_branch(graph_x, g_ei, g_bat, N_G, E_G,
               gW[0], gW[1], gW[2], gW[3], gW[4], gW[5], gW[6], gW[7], gW[8],
               buf0, buf1, agg, rowptr, cursor, srcs, bsums, pool, cnt);
    // Subgraph branch (reuses scratch)
    run_branch(subgraph_x, s_ei, s_bat, N_S, E_S,
               sW[0], sW[1], sW[2], sW[3], sW[4], sW[5], sW[6], sW[7], sW[8],
               buf0, buf1, agg, rowptr, cursor, srcs, bsums, pool + NB * 192, cnt + NB);

    // Concat + MLP
    cat_kernel<<<(NB * 448 + 255) / 256, 256>>>(pool, cnt, pool + NB * 192, cnt + NB, point, cat);
    fc_kernel<<<(NB * 600 * 32 + 255) / 256, 256>>>(cat, l1W, l1b, h1, NB, 448, 600, 1);
    fc_kernel<<<(NB * 256 * 32 + 255) / 256, 256>>>(h1, l2W, l2b, h2, NB, 600, 256, 1);
    fc_kernel<<<(NB * 64 * 32 + 255) / 256, 256>>>(h2, l3W, l3b, out, NB, 256, 64, 0);
    (void)n_in; (void)out_size;
}

// round 3
// speedup vs baseline: 1.8565x; 1.1376x over previous
#include <cuda_runtime.h>
#include <math.h>
#include <stdint.h>

// ---------------------------------------------------------------------------
// Problem constants
// ---------------------------------------------------------------------------
#define N_G 50000
#define E_G 800000
#define N_S 10000
#define E_S 160000
#define NF 64
#define NB 8

// ---------------------------------------------------------------------------
// Scratch (device globals; allocation-free)
// ---------------------------------------------------------------------------
__device__ float g_buf0[(size_t)N_G * 256];
__device__ float g_buf1[(size_t)N_G * 256];
__device__ float g_agg [(size_t)N_G * 256];
__device__ float g_pool[2 * NB * 192];
__device__ float g_cnt [2 * NB];
__device__ float g_cat [NB * 448];
__device__ float g_h1  [NB * 600];
__device__ float g_h2  [NB * 256];
__device__ int   g_rowptr[N_G + 1];
__device__ int   g_cursor[N_G];
__device__ int   g_srcs  [E_G];
__device__ int   g_bsums [512];

// ---------------------------------------------------------------------------
// CSR build: histogram -> 2-level exclusive scan -> cursor fill
// ---------------------------------------------------------------------------
__global__ void hist_kernel(const int* __restrict__ dst, int* __restrict__ counts, int E)
{
    int e = blockIdx.x * blockDim.x + threadIdx.x;
    if (e < E) atomicAdd(&counts[dst[e]], 1);
}

__global__ void scan1_kernel(const int* __restrict__ counts, int* __restrict__ bsums, int N)
{
    __shared__ int s[256];
    int i = blockIdx.x * 256 + threadIdx.x;
    int v = (i < N) ? counts[i] : 0;
    s[threadIdx.x] = v;
    __syncthreads();
    for (int off = 128; off > 0; off >>= 1) {
        if (threadIdx.x < off) s[threadIdx.x] += s[threadIdx.x + off];
        __syncthreads();
    }
    if (threadIdx.x == 0) bsums[blockIdx.x] = s[0];
}

__global__ void scan2_kernel(int* __restrict__ bsums, int nb, int* __restrict__ rowptr,
                             int N, int E)
{
    __shared__ int s[256];
    int tid = threadIdx.x;
    int v = (tid < nb) ? bsums[tid] : 0;
    s[tid] = v;
    __syncthreads();
    for (int off = 1; off < 256; off <<= 1) {
        int t = (tid >= off) ? s[tid - off] : 0;
        __syncthreads();
        s[tid] += t;
        __syncthreads();
    }
    if (tid < nb) bsums[tid] = s[tid] - v;
    if (tid == 0) rowptr[N] = E;
}

__global__ void scan3_kernel(int* __restrict__ rowptr, const int* __restrict__ bsums,
                             int* __restrict__ cursor, int N)
{
    __shared__ int s[256];
    int tid = threadIdx.x;
    int i = blockIdx.x * 256 + tid;
    int v = (i < N) ? rowptr[i] : 0;
    s[tid] = v;
    __syncthreads();
    for (int off = 1; off < 256; off <<= 1) {
        int t = (tid >= off) ? s[tid - off] : 0;
        __syncthreads();
        s[tid] += t;
        __syncthreads();
    }
    if (i < N) {
        int val = s[tid] - v + bsums[blockIdx.x];
        rowptr[i] = val;
        cursor[i] = val;
    }
}

__global__ void fill_kernel(const int* __restrict__ src, const int* __restrict__ dst,
                            int* __restrict__ cursor, int* __restrict__ srcs, int E)
{
    int e = blockIdx.x * blockDim.x + threadIdx.x;
    if (e >= E) return;
    int d = dst[e];
    int p = atomicAdd(&cursor[d], 1);
    srcs[p] = src[e];
}

// ---------------------------------------------------------------------------
// CSR gather aggregation (float4): agg[n][c4] = sum_e x4[srcs[e]][c4]
// C4 in {16,32,64}; block = 256 threads covers (256>>lgC4) nodes
// ---------------------------------------------------------------------------
__global__ __launch_bounds__(256)
void gather_kernel(const float4* __restrict__ x4, const int* __restrict__ rowptr,
                   const int* __restrict__ srcs, float4* __restrict__ agg4,
                   int N, int C4, int lgC4)
{
    int c    = threadIdx.x & (C4 - 1);
    int node = blockIdx.x * (256 >> lgC4) + (threadIdx.x >> lgC4);
    if (node >= N) return;
    int b = rowptr[node];
    int e = rowptr[node + 1];
    float4 a0 = make_float4(0.f, 0.f, 0.f, 0.f);
    float4 a1 = a0;
    int i = b;
    for (; i + 2 <= e; i += 2) {
        int s0 = srcs[i], s1 = srcs[i + 1];
        float4 v = x4[(size_t)s0 * C4 + c];
        float4 w = x4[(size_t)s1 * C4 + c];
        a0.x += v.x; a0.y += v.y; a0.z += v.z; a0.w += v.w;
        a1.x += w.x; a1.y += w.y; a1.z += w.z; a1.w += w.w;
    }
    if (i < e) {
        float4 v = x4[(size_t)srcs[i] * C4 + c];
        a0.x += v.x; a0.y += v.y; a0.z += v.z; a0.w += v.w;
    }
    a0.x += a1.x; a0.y += a1.y; a0.z += a1.z; a0.w += a1.w;
    agg4[(size_t)node * C4 + c] = a0;
}

// ---------------------------------------------------------------------------
// Tensor-core fused dual GEMM + bias + ELU (3xTF32 compensated)
//   out[N][CO] = elu(A1 @ W1^T + A2 @ W2^T + bias)
// 128x64 block tile, BK=16, 256 threads = 8 warps (4m x 2n), 32x32 warp tile.
// ---------------------------------------------------------------------------
#define BM 128
#define BN 64
#define BK 16
#define ASTR 136   // stride%32 == 8 -> frag banks = 8k+m, conflict-free
#define BSTR 72

__device__ __forceinline__ uint32_t f2tf32(float x)
{
    uint32_t r;
    asm("cvt.rna.tf32.f32 %0, %1;" : "=r"(r) : "f"(x));
    return r;
}

__device__ __forceinline__ void mma_tf32(float* d, const uint32_t* a, const uint32_t* b)
{
    asm("mma.sync.aligned.m16n8k8.row.col.f32.tf32.tf32.f32 "
        "{%0,%1,%2,%3}, {%4,%5,%6,%7}, {%8,%9}, {%0,%1,%2,%3};\n"
        : "+f"(d[0]), "+f"(d[1]), "+f"(d[2]), "+f"(d[3])
        : "r"(a[0]), "r"(a[1]), "r"(a[2]), "r"(a[3]), "r"(b[0]), "r"(b[1]));
}

__global__ __launch_bounds__(256)
void gemm_dual_elu(const float* __restrict__ A1, const float* __restrict__ A2,
                   const float* __restrict__ W1, const float* __restrict__ W2,
                   const float* __restrict__ bias, float* __restrict__ out,
                   int N, int C, int CO)
{
    __shared__ uint32_t As[2][BK][ASTR];   // [split hi/lo][k][m]
    __shared__ uint32_t Bs[2][BK][BSTR];   // [split hi/lo][k][n]

    const int tid  = threadIdx.x;
    const int row0 = blockIdx.x * BM;
    const int col0 = blockIdx.y * BN;

    // loader mapping: A: 128 threads x (8 k each); B: 64 threads x (4 k each)x4
    const int ar = tid & 127;               // row in tile
    const int ak = (tid >> 7) << 3;         // 0 or 8
    const int br = tid & 63;
    const int bk = ((tid >> 6) & 3) << 2;   // 0,4,8,12

    const int ga_row = row0 + ar;
    const int gb_row = col0 + br;           // always < CO

    // warp mapping
    const int w      = tid >> 5;
    const int lane   = tid & 31;
    const int lane4  = lane >> 2;           // 0..7
    const int lanek  = lane & 3;            // 0..3
    const int warp_m = (w & 3) * 32;
    const int warp_n = (w >> 2) * 32;

    float acc[2][4][4];
#pragma unroll
    for (int mt = 0; mt < 2; mt++)
#pragma unroll
        for (int nt = 0; nt < 4; nt++)
#pragma unroll
            for (int r = 0; r < 4; r++) acc[mt][nt][r] = 0.f;

    const int Ktot = 2 * C;
    const int nk   = Ktot / BK;

    float4 av0, av1, bv;

    // prefetch tile 0
    {
        av0 = make_float4(0.f, 0.f, 0.f, 0.f); av1 = av0;
        if (ga_row < N) {
            av0 = *(const float4*)(A1 + (size_t)ga_row * C + ak);
            av1 = *(const float4*)(A1 + (size_t)ga_row * C + ak + 4);
        }
        bv = *(const float4*)(W1 + (size_t)gb_row * C + bk);
    }

    for (int t = 0; t < nk; t++) {
        __syncthreads();
        // store (with tf32 hi/lo split)
        {
            float af[8] = {av0.x, av0.y, av0.z, av0.w, av1.x, av1.y, av1.z, av1.w};
#pragma unroll
            for (int j = 0; j < 8; j++) {
                uint32_t hi = f2tf32(af[j]);
                uint32_t lo = f2tf32(af[j] - __uint_as_float(hi));
                As[0][ak + j][ar] = hi;
                As[1][ak + j][ar] = lo;
            }
            float bf[4] = {bv.x, bv.y, bv.z, bv.w};
#pragma unroll
            for (int j = 0; j < 4; j++) {
                uint32_t hi = f2tf32(bf[j]);
                uint32_t lo = f2tf32(bf[j] - __uint_as_float(hi));
                Bs[0][bk + j][br] = hi;
                Bs[1][bk + j][br] = lo;
            }
        }
        __syncthreads();

        // prefetch next tile
        if (t + 1 < nk) {
            int kt = (t + 1) * BK;
            const float* A; const float* W; int kb;
            if (kt < C) { A = A1; W = W1; kb = kt; }
            else        { A = A2; W = W2; kb = kt - C; }
            av0 = make_float4(0.f, 0.f, 0.f, 0.f); av1 = av0;
            if (ga_row < N) {
                av0 = *(const float4*)(A + (size_t)ga_row * C + kb + ak);
                av1 = *(const float4*)(A + (size_t)ga_row * C + kb + ak + 4);
            }
            bv = *(const float4*)(W + (size_t)gb_row * C + kb + bk);
        }

        // compute: two k8 steps
#pragma unroll
        for (int ks = 0; ks < 2; ks++) {
            const int kk = ks * 8 + lanek;
            uint32_t aH[2][4], aL[2][4], bH[4][2], bL[4][2];
#pragma unroll
            for (int mt = 0; mt < 2; mt++) {
                int m = warp_m + mt * 16 + lane4;
                aH[mt][0] = As[0][kk][m];     aH[mt][1] = As[0][kk][m + 8];
                aH[mt][2] = As[0][kk + 4][m]; aH[mt][3] = As[0][kk + 4][m + 8];
                aL[mt][0] = As[1][kk][m];     aL[mt][1] = As[1][kk][m + 8];
                aL[mt][2] = As[1][kk + 4][m]; aL[mt][3] = As[1][kk + 4][m + 8];
            }
#pragma unroll
            for (int nt = 0; nt < 4; nt++) {
                int n = warp_n + nt * 8 + lane4;
                bH[nt][0] = Bs[0][kk][n]; bH[nt][1] = Bs[0][kk + 4][n];
                bL[nt][0] = Bs[1][kk][n]; bL[nt][1] = Bs[1][kk + 4][n];
            }
#pragma unroll
            for (int mt = 0; mt < 2; mt++)
#pragma unroll
                for (int nt = 0; nt < 4; nt++) {
                    mma_tf32(acc[mt][nt], aL[mt], bH[nt]);
                    mma_tf32(acc[mt][nt], aH[mt], bL[nt]);
                    mma_tf32(acc[mt][nt], aH[mt], bH[nt]);
                }
        }
    }

    // epilogue: bias + ELU, float2 stores
#pragma unroll
    for (int nt = 0; nt < 4; nt++) {
        int c = col0 + warp_n + nt * 8 + lanek * 2;
        float b0f = bias[c];
        float b1f = bias[c + 1];
#pragma unroll
        for (int mt = 0; mt < 2; mt++) {
            int r0 = row0 + warp_m + mt * 16 + lane4;
            int r1 = r0 + 8;
            if (r0 < N) {
                float v0 = acc[mt][nt][0] + b0f;
                float v1 = acc[mt][nt][1] + b1f;
                v0 = v0 > 0.f ? v0 : expm1f(v0);
                v1 = v1 > 0.f ? v1 : expm1f(v1);
                *(float2*)(out + (size_t)r0 * CO + c) = make_float2(v0, v1);
            }
            if (r1 < N) {
                float v2 = acc[mt][nt][2] + b0f;
                float v3 = acc[mt][nt][3] + b1f;
                v2 = v2 > 0.f ? v2 : expm1f(v2);
                v3 = v3 > 0.f ? v3 : expm1f(v3);
                *(float2*)(out + (size_t)r1 * CO + c) = make_float2(v2, v3);
            }
        }
    }
}

// ---------------------------------------------------------------------------
// Mean-pool (C fixed at 192), smem-staged
// ---------------------------------------------------------------------------
__global__ __launch_bounds__(256)
void pool_sum_kernel(const float* __restrict__ x, const int* __restrict__ batch,
                     float* __restrict__ sums, int N)
{
    __shared__ float acc[NB * 192];
    for (int i = threadIdx.x; i < NB * 192; i += 256) acc[i] = 0.f;
    __syncthreads();

    int n0  = blockIdx.x * 256;
    int cnt = N - n0; if (cnt > 256) cnt = 256;
    int total = cnt * 192;
    for (int idx = threadIdx.x; idx < total; idx += 256) {
        int nl = idx / 192;
        int c  = idx - nl * 192;
        int n  = n0 + nl;
        atomicAdd(&acc[batch[n] * 192 + c], x[(size_t)n * 192 + c]);
    }
    __syncthreads();
    for (int i = threadIdx.x; i < NB * 192; i += 256) {
        float v = acc[i];
        if (v != 0.f) atomicAdd(&sums[i], v);
    }
}

__global__ void count_kernel(const int* __restrict__ batch, float* __restrict__ cnt, int N)
{
    __shared__ float c[NB];
    if (threadIdx.x < NB) c[threadIdx.x] = 0.f;
    __syncthreads();
    int n = blockIdx.x * blockDim.x + threadIdx.x;
    if (n < N) atomicAdd(&c[batch[n]], 1.f);
    __syncthreads();
    if (threadIdx.x < NB) {
        float v = c[threadIdx.x];
        if (v != 0.f) atomicAdd(&cnt[threadIdx.x], v);
    }
}

__global__ void cat_kernel(const float* __restrict__ sums1, const float* __restrict__ cnt1,
                           const float* __restrict__ sums2, const float* __restrict__ cnt2,
                           const float* __restrict__ point, float* __restrict__ cat)
{
    int i = blockIdx.x * blockDim.x + threadIdx.x;
    if (i >= NB * 448) return;
    int b = i / 448, c = i - b * 448;
    float v;
    if (c < 192)      v = sums1[b * 192 + c]         / fmaxf(cnt1[b], 1.f);
    else if (c < 384) v = sums2[b * 192 + (c - 192)] / fmaxf(cnt2[b], 1.f);
    else              v = point[b * NF + (c - 384)];
    cat[i] = v;
}

__global__ void fc_kernel(const float* __restrict__ in, const float* __restrict__ W,
                          const float* __restrict__ bias, float* __restrict__ out,
                          int Bn, int K, int O, int act)
{
    int warp = (blockIdx.x * blockDim.x + threadIdx.x) >> 5;
    int lane = threadIdx.x & 31;
    if (warp >= Bn * O) return;
    int b = warp / O, o = warp - b * O;
    const float* ip = in + (size_t)b * K;
    const float* wp = W  + (size_t)o * K;
    float s = 0.f;
    for (int k = lane; k < K; k += 32) s += ip[k] * wp[k];
#pragma unroll
    for (int off = 16; off; off >>= 1) s += __shfl_xor_sync(0xFFFFFFFFu, s, off);
    if (lane == 0) {
        s += bias[o];
        if (act) s = fmaxf(s, 0.f);
        out[(size_t)b * O + o] = s;
    }
}

// ---------------------------------------------------------------------------
// Host-side branch driver
// ---------------------------------------------------------------------------
static void run_branch(const float* x_in, const int* ei, const int* batch,
                       int N, int E,
                       const float* W1r, const float* W1n, const float* B1,
                       const float* W2r, const float* W2n, const float* B2,
                       const float* W3r, const float* W3n, const float* B3,
                       float* buf0, float* buf1, float* agg,
                       int* rowptr, int* cursor, int* srcs, int* bsums,
                       float* sums, float* cnt)
{
    const int* src = ei;
    const int* dst = ei + E;

    cudaMemsetAsync(rowptr, 0, (size_t)(N + 1) * sizeof(int));
    hist_kernel<<<(E + 255) / 256, 256>>>(dst, rowptr, E);
    int nb = (N + 255) / 256;
    scan1_kernel<<<nb, 256>>>(rowptr, bsums, N);
    scan2_kernel<<<1, 256>>>(bsums, nb, rowptr, N, E);
    scan3_kernel<<<nb, 256>>>(rowptr, bsums, cursor, N);
    fill_kernel<<<(E + 255) / 256, 256>>>(src, dst, cursor, srcs, E);

    // L1: C=64 -> CO=128
    gather_kernel<<<(N + 15) / 16, 256>>>((const float4*)x_in, rowptr, srcs,
                                          (float4*)agg, N, 16, 4);
    gemm_dual_elu<<<dim3((N + BM - 1) / BM, 128 / BN), 256>>>(agg, x_in, W1r, W1n, B1, buf0, N, 64, 128);
    // L2: C=128 -> CO=256
    gather_kernel<<<(N + 7) / 8, 256>>>((const float4*)buf0, rowptr, srcs,
                                        (float4*)agg, N, 32, 5);
    gemm_dual_elu<<<dim3((N + BM - 1) / BM, 256 / BN), 256>>>(agg, buf0, W2r, W2n, B2, buf1, N, 128, 256);
    // L3: C=256 -> CO=192
    gather_kernel<<<(N + 3) / 4, 256>>>((const float4*)buf1, rowptr, srcs,
                                        (float4*)agg, N, 64, 6);
    gemm_dual_elu<<<dim3((N + BM - 1) / BM, 192 / BN), 256>>>(agg, buf1, W3r, W3n, B3, buf0, N, 256, 192);

    pool_sum_kernel<<<(N + 255) / 256, 256>>>(buf0, batch, sums, N);
    count_kernel  <<<(N + 255) / 256, 256>>>(batch, cnt, N);
}

// ---------------------------------------------------------------------------
// kernel_launch
// ---------------------------------------------------------------------------
extern "C" void kernel_launch(void* const* d_in, const int* in_sizes, int n_in,
                              void* d_out, int out_size)
{
    int IDX[31];
    bool dict_order = (in_sizes[3] == 2 * E_G);
    if (dict_order) {
        int m[31] = {0,1,2, 7,8,9,10,11,12,13,14,15, 16,17,18,19,20,21,22,23,24,
                     25,26,27,28,29,30, 3,4,5,6};
        for (int i = 0; i < 31; i++) IDX[i] = m[i];
    } else {
        for (int i = 0; i < 31; i++) IDX[i] = i;
    }
    const float* graph_x    = (const float*)d_in[IDX[0]];
    const float* subgraph_x = (const float*)d_in[IDX[1]];
    const float* point      = (const float*)d_in[IDX[2]];
    const float* gW[9]; const float* sW[9];
    for (int i = 0; i < 9; i++) gW[i] = (const float*)d_in[IDX[3 + i]];
    for (int i = 0; i < 9; i++) sW[i] = (const float*)d_in[IDX[12 + i]];
    const float* l1W = (const float*)d_in[IDX[21]];
    const float* l1b = (const float*)d_in[IDX[22]];
    const float* l2W = (const float*)d_in[IDX[23]];
    const float* l2b = (const float*)d_in[IDX[24]];
    const float* l3W = (const float*)d_in[IDX[25]];
    const float* l3b = (const float*)d_in[IDX[26]];
    const int* g_ei   = (const int*)d_in[IDX[27]];
    const int* g_bat  = (const int*)d_in[IDX[28]];
    const int* s_ei   = (const int*)d_in[IDX[29]];
    const int* s_bat  = (const int*)d_in[IDX[30]];

    float *buf0, *buf1, *agg, *pool, *cnt, *cat, *h1, *h2;
    int *rowptr, *cursor, *srcs, *bsums;
    cudaGetSymbolAddress((void**)&buf0, g_buf0);
    cudaGetSymbolAddress((void**)&buf1, g_buf1);
    cudaGetSymbolAddress((void**)&agg,  g_agg);
    cudaGetSymbolAddress((void**)&pool, g_pool);
    cudaGetSymbolAddress((void**)&cnt,  g_cnt);
    cudaGetSymbolAddress((void**)&cat,  g_cat);
    cudaGetSymbolAddress((void**)&h1,   g_h1);
    cudaGetSymbolAddress((void**)&h2,   g_h2);
    cudaGetSymbolAddress((void**)&rowptr, g_rowptr);
    cudaGetSymbolAddress((void**)&cursor, g_cursor);
    cudaGetSymbolAddress((void**)&srcs,   g_srcs);
    cudaGetSymbolAddress((void**)&bsums,  g_bsums);

    float* out = (float*)d_out;

    cudaMemsetAsync(pool, 0, 2 * NB * 192 * sizeof(float));
    cudaMemsetAsync(cnt,  0, 2 * NB * sizeof(float));

    run_branch(graph_x, g_ei, g_bat, N_G, E_G,
               gW[0], gW[1], gW[2], gW[3], gW[4], gW[5], gW[6], gW[7], gW[8],
               buf0, buf1, agg, rowptr, cursor, srcs, bsums, pool, cnt);
    run_branch(subgraph_x, s_ei, s_bat, N_S, E_S,
               sW[0], sW[1], sW[2], sW[3], sW[4], sW[5], sW[6], sW[7], sW[8],
               buf0, buf1, agg, rowptr, cursor, srcs, bsums, pool + NB * 192, cnt + NB);

    cat_kernel<<<(NB * 448 + 255) / 256, 256>>>(pool, cnt, pool + NB * 192, cnt + NB, point, cat);
    fc_kernel<<<(NB * 600 * 32 + 255) / 256, 256>>>(cat, l1W, l1b, h1, NB, 448, 600, 1);
    fc_kernel<<<(NB * 256 * 32 + 255) / 256, 256>>>(h1, l2W, l2b, h2, NB, 600, 256, 1);
    fc_kernel<<<(NB * 64 * 32 + 255) / 256, 256>>>(h2, l3W, l3b, out, NB, 256, 64, 0);
    (void)n_in; (void)out_size;
}